// round 4
// baseline (speedup 1.0000x reference)
#include <cuda_runtime.h>

#define N_ENT  100000
#define EMB    64
#define NREL   32
#define NEDGE  1000000
#define WARPS  8
#define EPB    4

typedef unsigned long long ull;

// ---------------- static device scratch (no allocation allowed) ----------------
__device__ float g_Q[N_ENT * EMB];       // (agg @ q_w)
__device__ float g_agg[N_ENT * EMB];     // agg after hop 1
__device__ int   g_deg[N_ENT];
__device__ int   g_rowptr[N_ENT + 1];
__device__ int   g_cursor[N_ENT];
__device__ int   g_tailc[NEDGE];         // CSR-ordered tails
__device__ int   g_typec[NEDGE];         // CSR-ordered edge types

// ---------------- PTX helpers (sm_100+) ----------------
__device__ __forceinline__ ull fma2(ull a, ull b, ull c) {
    ull d;
    asm("fma.rn.f32x2 %0, %1, %2, %3;" : "=l"(d) : "l"(a), "l"(b), "l"(c));
    return d;
}
__device__ __forceinline__ float2 up2(ull v) {
    float2 f;
    asm("mov.b64 {%0, %1}, %2;" : "=f"(f.x), "=f"(f.y) : "l"(v));
    return f;
}
__device__ __forceinline__ float tanha(float x) {
    float y;
    asm("tanh.approx.f32 %0, %1;" : "=f"(y) : "f"(x));
    return y;
}
__device__ __forceinline__ float neg_inf() { return __int_as_float(0xff800000U); }

// ---------------- CSR build ----------------
__global__ void zero_deg_kernel() {
    int i = blockIdx.x * blockDim.x + threadIdx.x;
    if (i < N_ENT) g_deg[i] = 0;
}

__global__ void count_kernel(const int* __restrict__ head) {
    int e = blockIdx.x * blockDim.x + threadIdx.x;
    if (e < NEDGE) atomicAdd(&g_deg[head[e]], 1);
}

// single-block sequential-chunk scan (runs once per launch; ~100k elems)
__global__ void scan_kernel() {
    __shared__ int sh[1024];
    __shared__ int carry_s;
    int tid = threadIdx.x;
    if (tid == 0) carry_s = 0;
    __syncthreads();
    for (int base = 0; base < N_ENT; base += 1024) {
        int i = base + tid;
        int v = (i < N_ENT) ? g_deg[i] : 0;
        sh[tid] = v;
        __syncthreads();
        for (int off = 1; off < 1024; off <<= 1) {
            int t = (tid >= off) ? sh[tid - off] : 0;
            __syncthreads();
            sh[tid] += t;
            __syncthreads();
        }
        int excl = sh[tid] - v + carry_s;
        if (i < N_ENT) { g_rowptr[i] = excl; g_cursor[i] = excl; }
        __syncthreads();
        if (tid == 1023) carry_s += sh[1023];
        __syncthreads();
    }
    if (tid == 0) g_rowptr[N_ENT] = carry_s;
}

__global__ void fill_kernel(const int* __restrict__ head,
                            const int* __restrict__ tail,
                            const int* __restrict__ etype) {
    int e = blockIdx.x * blockDim.x + threadIdx.x;
    if (e < NEDGE) {
        int h = head[e];
        int pos = atomicAdd(&g_cursor[h], 1);
        g_tailc[pos] = tail[e];
        g_typec[pos] = etype[e];
    }
}

// ---------------- Q = agg @ q_w   (warp per row, packed f32x2 FMA) ----------------
__global__ void gemmq_kernel(const float* agg_in, const float* __restrict__ qw) {
    __shared__ ull qsm[EMB * 32];      // qw[i][2l],qw[i][2l+1] packed
    __shared__ ull xs[WARPS][EMB];     // duplicated row values
    const float* A = agg_in ? agg_in : g_agg;
    const ull* qw64 = (const ull*)qw;
    for (int idx = threadIdx.x; idx < EMB * 32; idx += blockDim.x) qsm[idx] = qw64[idx];
    __syncthreads();
    int w = threadIdx.x >> 5, l = threadIdx.x & 31;
    const float2* A2 = (const float2*)A;
    for (int row = blockIdx.x * WARPS + w; row < N_ENT; row += gridDim.x * WARPS) {
        float2 a2 = A2[row * 32 + l];
        ((float4*)xs[w])[l] = make_float4(a2.x, a2.x, a2.y, a2.y);
        __syncwarp();
        ull acc = 0ull;
        #pragma unroll 8
        for (int i = 0; i < EMB; i++) acc = fma2(qsm[i * 32 + l], xs[w][i], acc);
        float2 r = up2(acc);
        ((float2*)g_Q)[row * 32 + l] = r;
        __syncwarp();
    }
}

// ---------------- fused per-head hop kernel ----------------
// warp per head: edge GEMM (EPB-batched), tanh-attention, online softmax,
// scatter-mean, l2norm, kg accumulation. No atomics, no intermediate edge buffers.
__global__ void fused_kernel(const float* agg_in,
                             const float* __restrict__ edge_emb,
                             const float* __restrict__ kw,
                             const float* __restrict__ ent,
                             float* kg, int accumulate, int write_agg) {
    __shared__ ull ksm[EMB * 32];           // 16KB: kw[i][2l..2l+1] packed
    __shared__ ull relsm[NREL * 32];        // 8KB : rel[r][2l..2l+1] packed
    __shared__ ull xs[WARPS * EPB][EMB];    // 16KB: duplicated x values per edge slot
    const float* A = agg_in ? agg_in : g_agg;
    const ull* kw64 = (const ull*)kw;
    const ull* re64 = (const ull*)edge_emb;
    for (int idx = threadIdx.x; idx < EMB * 32; idx += blockDim.x) ksm[idx] = kw64[idx];
    for (int idx = threadIdx.x; idx < NREL * 32; idx += blockDim.x) relsm[idx] = re64[idx];
    __syncthreads();

    int w = threadIdx.x >> 5, l = threadIdx.x & 31;
    const float2* A2 = (const float2*)A;
    const float2* Q2 = (const float2*)g_Q;
    const float2* E2 = (const float2*)ent;
    float2* KG2 = (float2*)kg;

    for (int h = blockIdx.x * WARPS + w; h < N_ENT; h += gridDim.x * WARPS) {
        int rs = g_rowptr[h];
        int re = g_rowptr[h + 1];
        int deg = re - rs;
        float2 q = Q2[h * 32 + l];
        float m = neg_inf(), ssum = 0.f, a0 = 0.f, a1 = 0.f;

        for (int j0 = rs; j0 < re; j0 += EPB) {
            int nv = re - j0; if (nv > EPB) nv = EPB;
            float x0[EPB], x1[EPB];
            #pragma unroll
            for (int e = 0; e < EPB; e++) {
                float xa = 0.f, xb = 0.f;
                if (e < nv) {
                    int t = g_tailc[j0 + e];
                    int r = g_typec[j0 + e];
                    float2 ag = A2[t * 32 + l];
                    float2 rr = up2(relsm[r * 32 + l]);
                    xa = rr.x * ag.x;
                    xb = rr.y * ag.y;
                }
                x0[e] = xa; x1[e] = xb;
                ((float4*)xs[w * EPB + e])[l] = make_float4(xa, xa, xb, xb);
            }
            __syncwarp();

            ull acc[EPB];
            #pragma unroll
            for (int e = 0; e < EPB; e++) acc[e] = 0ull;
            #pragma unroll 8
            for (int i = 0; i < EMB; i++) {
                ull kv = ksm[i * 32 + l];           // amortized over EPB edges
                #pragma unroll
                for (int e = 0; e < EPB; e++)
                    acc[e] = fma2(kv, xs[w * EPB + e][i], acc[e]);
            }

            float att[EPB];
            #pragma unroll
            for (int e = 0; e < EPB; e++) {
                float2 y = up2(acc[e]);
                float d = tanha(y.x) * q.x + tanha(y.y) * q.y;
                #pragma unroll
                for (int o = 16; o; o >>= 1) d += __shfl_xor_sync(0xffffffffu, d, o);
                att[e] = d;
            }

            // online softmax + message accumulation (x kept in registers)
            #pragma unroll
            for (int e = 0; e < EPB; e++) {
                if (e < nv) {
                    float nm = fmaxf(m, att[e]);
                    float c  = __expf(m - nm);       // m=-inf first time -> 0
                    float p  = __expf(att[e] - nm);
                    ssum = ssum * c + p;
                    a0   = a0 * c + p * x0[e];
                    a1   = a1 * c + p * x1[e];
                    m = nm;
                }
            }
            __syncwarp();   // xs reads done before next batch overwrites
        }

        float v0 = 0.f, v1 = 0.f;
        if (deg > 0) {
            float inv = 1.f / (ssum * (float)deg);   // softmax denom * scatter_mean count
            v0 = a0 * inv; v1 = a1 * inv;
        }
        float sq = v0 * v0 + v1 * v1;
        #pragma unroll
        for (int o = 16; o; o >>= 1) sq += __shfl_xor_sync(0xffffffffu, sq, o);
        float rn = 1.f / fmaxf(sqrtf(sq), 1e-12f);   // matches F.normalize eps path
        v0 *= rn; v1 *= rn;

        if (write_agg) ((float2*)g_agg)[h * 32 + l] = make_float2(v0, v1);
        float2 e2 = E2[h * 32 + l];
        float2 o2;
        if (accumulate) {
            float2 kold = KG2[h * 32 + l];
            o2 = make_float2(kold.x + v0 + e2.x, kold.y + v1 + e2.y);
        } else {
            o2 = make_float2(v0 + e2.x, v1 + e2.y);
        }
        KG2[h * 32 + l] = o2;
    }
}

// ---------------- launch ----------------
extern "C" void kernel_launch(void* const* d_in, const int* in_sizes, int n_in,
                              void* d_out, int out_size) {
    const float* ent      = (const float*)d_in[0];   // entity_emb [N,64]
    const float* edge_emb = (const float*)d_in[1];   // [32,64]
    const float* qw       = (const float*)d_in[2];   // [64,64]
    const float* kw       = (const float*)d_in[3];   // [64,64]
    const int*   eidx     = (const int*)d_in[4];     // [2,E]
    const int*   etype    = (const int*)d_in[5];     // [E]
    const int* head = eidx;
    const int* tail = eidx + NEDGE;
    float* kg = (float*)d_out;

    // CSR build (head is identical for both hops -> build once per launch)
    zero_deg_kernel<<<(N_ENT + 255) / 256, 256>>>();
    count_kernel<<<(NEDGE + 255) / 256, 256>>>(head);
    scan_kernel<<<1, 1024>>>();
    fill_kernel<<<(NEDGE + 255) / 256, 256>>>(head, tail, etype);

    // hop 1: agg = entity_emb
    gemmq_kernel<<<2048, 256>>>(ent, qw);
    fused_kernel<<<3125, 256>>>(ent, edge_emb, kw, ent, kg, /*accumulate=*/0, /*write_agg=*/1);

    // hop 2: agg = g_agg (nullptr selects the device-global buffer)
    gemmq_kernel<<<2048, 256>>>(nullptr, qw);
    fused_kernel<<<3125, 256>>>(nullptr, edge_emb, kw, ent, kg, /*accumulate=*/1, /*write_agg=*/0);
}

// round 8
// speedup vs baseline: 1.1303x; 1.1303x over previous
#include <cuda_runtime.h>

#define N_ENT  100000
#define EMB    64
#define NREL   32
#define NEDGE  1000000
#define WARPS  8
#define EPB    4
#define SCAN_BLKS ((N_ENT + 1023) / 1024)   // 98

typedef unsigned long long ull;

// ---------------- static device scratch (no allocation allowed) ----------------
__device__ float g_Q[N_ENT * EMB];       // (agg @ q_w)
__device__ float g_agg[N_ENT * EMB];     // agg after hop 1
__device__ int   g_deg[N_ENT];
__device__ int   g_rowptr[N_ENT + 1];
__device__ int   g_cursor[N_ENT];
__device__ int   g_bsum[128];            // scan block sums
__device__ int   g_tailc[NEDGE];         // CSR-ordered tails
__device__ int   g_typec[NEDGE];         // CSR-ordered edge types

// ---------------- PTX helpers (sm_100+) ----------------
__device__ __forceinline__ ull fma2(ull a, ull b, ull c) {
    ull d;
    asm("fma.rn.f32x2 %0, %1, %2, %3;" : "=l"(d) : "l"(a), "l"(b), "l"(c));
    return d;
}
__device__ __forceinline__ float2 up2(ull v) {
    float2 f;
    asm("mov.b64 {%0, %1}, %2;" : "=f"(f.x), "=f"(f.y) : "l"(v));
    return f;
}
__device__ __forceinline__ float tanha(float x) {
    float y;
    asm("tanh.approx.f32 %0, %1;" : "=f"(y) : "f"(x));
    return y;
}
__device__ __forceinline__ float neg_inf() { return __int_as_float(0xff800000U); }

// ---------------- CSR build ----------------
__global__ void zero_deg_kernel() {
    int i = blockIdx.x * blockDim.x + threadIdx.x;
    if (i < N_ENT) g_deg[i] = 0;
}

__global__ void count_kernel(const int* __restrict__ head) {
    int e = blockIdx.x * blockDim.x + threadIdx.x;
    if (e < NEDGE) atomicAdd(&g_deg[head[e]], 1);
}

// multi-block scan: phase 1 — per-block exclusive scan + block sums
__global__ void scan1_kernel() {
    __shared__ int sh[1024];
    int tid = threadIdx.x;
    int i = blockIdx.x * 1024 + tid;
    int v = (i < N_ENT) ? g_deg[i] : 0;
    sh[tid] = v;
    __syncthreads();
    for (int off = 1; off < 1024; off <<= 1) {
        int t = (tid >= off) ? sh[tid - off] : 0;
        __syncthreads();
        sh[tid] += t;
        __syncthreads();
    }
    if (i < N_ENT) g_rowptr[i] = sh[tid] - v;   // exclusive within block
    if (tid == 1023) g_bsum[blockIdx.x] = sh[1023];
}

// phase 2 — scan the (<=128) block sums in one small block
__global__ void scan2_kernel() {
    __shared__ int sh[128];
    int tid = threadIdx.x;
    int v = (tid < SCAN_BLKS) ? g_bsum[tid] : 0;
    sh[tid] = v;
    __syncthreads();
    for (int off = 1; off < 128; off <<= 1) {
        int t = (tid >= off) ? sh[tid - off] : 0;
        __syncthreads();
        sh[tid] += t;
        __syncthreads();
    }
    g_bsum[tid] = sh[tid] - v;                  // exclusive block offsets
}

// phase 3 — add block offsets, init cursors, close rowptr
__global__ void scan3_kernel() {
    int i = blockIdx.x * blockDim.x + threadIdx.x;
    if (i < N_ENT) {
        int r = g_rowptr[i] + g_bsum[i >> 10];
        g_rowptr[i] = r;
        g_cursor[i] = r;
    }
    if (i == 0) g_rowptr[N_ENT] = NEDGE;        // sum(deg) == NEDGE by construction
}

__global__ void fill_kernel(const int* __restrict__ head,
                            const int* __restrict__ tail,
                            const int* __restrict__ etype) {
    int e = blockIdx.x * blockDim.x + threadIdx.x;
    if (e < NEDGE) {
        int h = head[e];
        int pos = atomicAdd(&g_cursor[h], 1);
        g_tailc[pos] = tail[e];
        g_typec[pos] = etype[e];
    }
}

// ---------------- Q = agg @ q_w   (warp per row, packed f32x2 FMA) ----------------
__global__ void gemmq_kernel(const float* agg_in, const float* __restrict__ qw) {
    __shared__ ull qsm[EMB * 32];
    __shared__ ull xs[WARPS][EMB];
    const float* A = agg_in ? agg_in : g_agg;
    const ull* qw64 = (const ull*)qw;
    for (int idx = threadIdx.x; idx < EMB * 32; idx += blockDim.x) qsm[idx] = qw64[idx];
    __syncthreads();
    int w = threadIdx.x >> 5, l = threadIdx.x & 31;
    const float2* A2 = (const float2*)A;
    for (int row = blockIdx.x * WARPS + w; row < N_ENT; row += gridDim.x * WARPS) {
        float2 a2 = A2[row * 32 + l];
        ((float4*)xs[w])[l] = make_float4(a2.x, a2.x, a2.y, a2.y);
        __syncwarp();
        ull acc = 0ull;
        #pragma unroll 8
        for (int i = 0; i < EMB; i++) acc = fma2(qsm[i * 32 + l], xs[w][i], acc);
        float2 r = up2(acc);
        ((float2*)g_Q)[row * 32 + l] = r;
        __syncwarp();
    }
}

// ---------------- fused per-head hop kernel ----------------
// warp per head: edge GEMM (EPB-batched, LDS.128-vectorized, gather-prefetched),
// tanh-attention, online softmax, scatter-mean, l2norm, kg accumulation.
__global__ void fused_kernel(const float* agg_in,
                             const float* __restrict__ edge_emb,
                             const float* __restrict__ kw,
                             const float* __restrict__ ent,
                             float* kg, int accumulate, int write_agg) {
    // ksm layout: for i-pair p and lane l, entries [p*64 + 2l], [p*64 + 2l + 1]
    // hold (K[2p][2l],K[2p][2l+1]) and (K[2p+1][2l],K[2p+1][2l+1]) -> one LDS.128.
    __shared__ ull ksm[EMB * 32];           // 16KB
    __shared__ ull relsm[NREL * 32];        // 8KB
    __shared__ ull xs[WARPS * EPB][EMB];    // 16KB
    const float* A = agg_in ? agg_in : g_agg;
    const ull* kw64 = (const ull*)kw;
    const ull* re64 = (const ull*)edge_emb;
    for (int idx = threadIdx.x; idx < EMB * 32; idx += blockDim.x) {
        int i = idx >> 5, lc = idx & 31;
        ksm[(i >> 1) * 64 + lc * 2 + (i & 1)] = kw64[idx];
    }
    for (int idx = threadIdx.x; idx < NREL * 32; idx += blockDim.x) relsm[idx] = re64[idx];
    __syncthreads();

    int w = threadIdx.x >> 5, l = threadIdx.x & 31;
    const float2* A2 = (const float2*)A;
    const float2* Q2 = (const float2*)g_Q;
    const float2* E2 = (const float2*)ent;
    float2* KG2 = (float2*)kg;

    for (int h = blockIdx.x * WARPS + w; h < N_ENT; h += gridDim.x * WARPS) {
        int rs = g_rowptr[h];
        int re = g_rowptr[h + 1];
        int deg = re - rs;
        float2 q = Q2[h * 32 + l];
        float m = neg_inf(), ssum = 0.f, a0 = 0.f, a1 = 0.f;

        int nr[EPB];
        float2 nag[EPB];
        int j0 = rs;
        if (j0 < re) {                           // prefetch batch 0
            int nv = re - j0; if (nv > EPB) nv = EPB;
            #pragma unroll
            for (int e = 0; e < EPB; e++) {
                int t = (e < nv) ? g_tailc[j0 + e] : 0;
                nr[e] = (e < nv) ? g_typec[j0 + e] : 0;
                nag[e] = (e < nv) ? A2[t * 32 + l] : make_float2(0.f, 0.f);
            }
        }

        while (j0 < re) {
            int nv = re - j0; if (nv > EPB) nv = EPB;
            float x0[EPB], x1[EPB];
            #pragma unroll
            for (int e = 0; e < EPB; e++) {
                float2 rr = up2(relsm[nr[e] * 32 + l]);
                float xa = rr.x * nag[e].x;
                float xb = rr.y * nag[e].y;
                x0[e] = xa; x1[e] = xb;
                ((float4*)xs[w * EPB + e])[l] = make_float4(xa, xa, xb, xb);
            }

            int j1 = j0 + EPB;
            if (j1 < re) {                       // prefetch next batch (overlaps GEMM)
                int nv2 = re - j1; if (nv2 > EPB) nv2 = EPB;
                #pragma unroll
                for (int e = 0; e < EPB; e++) {
                    int t = (e < nv2) ? g_tailc[j1 + e] : 0;
                    nr[e] = (e < nv2) ? g_typec[j1 + e] : 0;
                    nag[e] = (e < nv2) ? A2[t * 32 + l] : make_float2(0.f, 0.f);
                }
            }
            __syncwarp();

            ull acc[EPB];
            #pragma unroll
            for (int e = 0; e < EPB; e++) acc[e] = 0ull;
            #pragma unroll 4
            for (int p = 0; p < 32; p++) {       // 2 K-rows per iteration, all LDS.128
                ulonglong2 kv = *(const ulonglong2*)&ksm[p * 64 + l * 2];
                #pragma unroll
                for (int e = 0; e < EPB; e++) {
                    ulonglong2 xv = *(const ulonglong2*)&xs[w * EPB + e][2 * p];
                    acc[e] = fma2(kv.x, xv.x, acc[e]);
                    acc[e] = fma2(kv.y, xv.y, acc[e]);
                }
            }

            float att[EPB];
            #pragma unroll
            for (int e = 0; e < EPB; e++) {
                float2 y = up2(acc[e]);
                float d = tanha(y.x) * q.x + tanha(y.y) * q.y;
                #pragma unroll
                for (int o = 16; o; o >>= 1) d += __shfl_xor_sync(0xffffffffu, d, o);
                att[e] = d;
            }

            #pragma unroll
            for (int e = 0; e < EPB; e++) {
                if (e < nv) {
                    float nm = fmaxf(m, att[e]);
                    float c  = __expf(m - nm);
                    float p  = __expf(att[e] - nm);
                    ssum = ssum * c + p;
                    a0   = a0 * c + p * x0[e];
                    a1   = a1 * c + p * x1[e];
                    m = nm;
                }
            }
            __syncwarp();
            j0 = j1;
        }

        float v0 = 0.f, v1 = 0.f;
        if (deg > 0) {
            float inv = 1.f / (ssum * (float)deg);
            v0 = a0 * inv; v1 = a1 * inv;
        }
        float sq = v0 * v0 + v1 * v1;
        #pragma unroll
        for (int o = 16; o; o >>= 1) sq += __shfl_xor_sync(0xffffffffu, sq, o);
        float rn = 1.f / fmaxf(sqrtf(sq), 1e-12f);
        v0 *= rn; v1 *= rn;

        if (write_agg) ((float2*)g_agg)[h * 32 + l] = make_float2(v0, v1);
        float2 e2 = E2[h * 32 + l];
        float2 o2;
        if (accumulate) {
            float2 kold = KG2[h * 32 + l];
            o2 = make_float2(kold.x + v0 + e2.x, kold.y + v1 + e2.y);
        } else {
            o2 = make_float2(v0 + e2.x, v1 + e2.y);
        }
        KG2[h * 32 + l] = o2;
    }
}

// ---------------- launch ----------------
extern "C" void kernel_launch(void* const* d_in, const int* in_sizes, int n_in,
                              void* d_out, int out_size) {
    const float* ent      = (const float*)d_in[0];
    const float* edge_emb = (const float*)d_in[1];
    const float* qw       = (const float*)d_in[2];
    const float* kw       = (const float*)d_in[3];
    const int*   eidx     = (const int*)d_in[4];
    const int*   etype    = (const int*)d_in[5];
    const int* head = eidx;
    const int* tail = eidx + NEDGE;
    float* kg = (float*)d_out;

    // CSR build (head identical across hops -> build once per launch)
    zero_deg_kernel<<<(N_ENT + 255) / 256, 256>>>();
    count_kernel<<<(NEDGE + 255) / 256, 256>>>(head);
    scan1_kernel<<<SCAN_BLKS, 1024>>>();
    scan2_kernel<<<1, 128>>>();
    scan3_kernel<<<(N_ENT + 255) / 256, 256>>>();
    fill_kernel<<<(NEDGE + 255) / 256, 256>>>(head, tail, etype);

    // hop 1: agg = entity_emb
    gemmq_kernel<<<2048, 256>>>(ent, qw);
    fused_kernel<<<3125, 256>>>(ent, edge_emb, kw, ent, kg, 0, 1);

    // hop 2: agg = g_agg
    gemmq_kernel<<<2048, 256>>>(nullptr, qw);
    fused_kernel<<<3125, 256>>>(nullptr, edge_emb, kw, ent, kg, 1, 0);
}

// round 9
// speedup vs baseline: 1.2173x; 1.0771x over previous
#include <cuda_runtime.h>

#define N_ENT  100000
#define EMB    64
#define NREL   32
#define NEDGE  1000000
#define WARPS  8
#define EPA    8    // edges per warp-batch in attA (edge-centric, always full)
#define EPB    4    // edges per batch in passB
#define SCAN_BLKS ((N_ENT + 1023) / 1024)   // 98

typedef unsigned long long ull;

// ---------------- static device scratch (no allocation allowed) ----------------
__device__ float g_Q[N_ENT * EMB];       // (agg @ q_w)
__device__ float g_agg[N_ENT * EMB];     // agg after hop 1
__device__ float g_att[NEDGE];           // attention logits (CSR order)
__device__ int   g_deg[N_ENT];
__device__ int   g_rowptr[N_ENT + 1];
__device__ int   g_cursor[N_ENT];
__device__ int   g_bsum[128];            // scan block sums
__device__ int   g_packc[NEDGE];         // CSR-ordered (tail | type<<17)
__device__ int   g_headc[NEDGE];         // CSR-ordered head

// ---------------- PTX helpers (sm_100+) ----------------
__device__ __forceinline__ ull fma2(ull a, ull b, ull c) {
    ull d;
    asm("fma.rn.f32x2 %0, %1, %2, %3;" : "=l"(d) : "l"(a), "l"(b), "l"(c));
    return d;
}
__device__ __forceinline__ float2 up2(ull v) {
    float2 f;
    asm("mov.b64 {%0, %1}, %2;" : "=f"(f.x), "=f"(f.y) : "l"(v));
    return f;
}
__device__ __forceinline__ float tanha(float x) {
    float y;
    asm("tanh.approx.f32 %0, %1;" : "=f"(y) : "f"(x));
    return y;
}
__device__ __forceinline__ float neg_inf() { return __int_as_float(0xff800000U); }

// ---------------- CSR build ----------------
__global__ void zero_deg_kernel() {
    int i = blockIdx.x * blockDim.x + threadIdx.x;
    if (i < N_ENT) g_deg[i] = 0;
}

__global__ void count_kernel(const int* __restrict__ head) {
    int e = blockIdx.x * blockDim.x + threadIdx.x;
    if (e < NEDGE) atomicAdd(&g_deg[head[e]], 1);
}

__global__ void scan1_kernel() {
    __shared__ int sh[1024];
    int tid = threadIdx.x;
    int i = blockIdx.x * 1024 + tid;
    int v = (i < N_ENT) ? g_deg[i] : 0;
    sh[tid] = v;
    __syncthreads();
    for (int off = 1; off < 1024; off <<= 1) {
        int t = (tid >= off) ? sh[tid - off] : 0;
        __syncthreads();
        sh[tid] += t;
        __syncthreads();
    }
    if (i < N_ENT) g_rowptr[i] = sh[tid] - v;
    if (tid == 1023) g_bsum[blockIdx.x] = sh[1023];
}

__global__ void scan2_kernel() {
    __shared__ int sh[128];
    int tid = threadIdx.x;
    int v = (tid < SCAN_BLKS) ? g_bsum[tid] : 0;
    sh[tid] = v;
    __syncthreads();
    for (int off = 1; off < 128; off <<= 1) {
        int t = (tid >= off) ? sh[tid - off] : 0;
        __syncthreads();
        sh[tid] += t;
        __syncthreads();
    }
    g_bsum[tid] = sh[tid] - v;
}

__global__ void scan3_kernel() {
    int i = blockIdx.x * blockDim.x + threadIdx.x;
    if (i < N_ENT) {
        int r = g_rowptr[i] + g_bsum[i >> 10];
        g_rowptr[i] = r;
        g_cursor[i] = r;
    }
    if (i == 0) g_rowptr[N_ENT] = NEDGE;
}

__global__ void fill_kernel(const int* __restrict__ head,
                            const int* __restrict__ tail,
                            const int* __restrict__ etype) {
    int e = blockIdx.x * blockDim.x + threadIdx.x;
    if (e < NEDGE) {
        int h = head[e];
        int pos = atomicAdd(&g_cursor[h], 1);
        g_packc[pos] = tail[e] | (etype[e] << 17);   // N_ENT < 2^17, NREL < 2^5
        g_headc[pos] = h;
    }
}

// ---------------- Q = agg @ q_w   (warp per row, packed f32x2 FMA) ----------------
__global__ void gemmq_kernel(const float* agg_in, const float* __restrict__ qw) {
    __shared__ ull qsm[EMB * 32];
    __shared__ ull xs[WARPS][EMB];
    const float* A = agg_in ? agg_in : g_agg;
    const ull* qw64 = (const ull*)qw;
    for (int idx = threadIdx.x; idx < EMB * 32; idx += blockDim.x) qsm[idx] = qw64[idx];
    __syncthreads();
    int w = threadIdx.x >> 5, l = threadIdx.x & 31;
    const float2* A2 = (const float2*)A;
    for (int row = blockIdx.x * WARPS + w; row < N_ENT; row += gridDim.x * WARPS) {
        float2 a2 = A2[row * 32 + l];
        ((float4*)xs[w])[l] = make_float4(a2.x, a2.x, a2.y, a2.y);
        __syncwarp();
        ull acc = 0ull;
        #pragma unroll 8
        for (int i = 0; i < EMB; i++) acc = fma2(qsm[i * 32 + l], xs[w][i], acc);
        float2 r = up2(acc);
        ((float2*)g_Q)[row * 32 + l] = r;
        __syncwarp();
    }
}

// ---------------- pass A: attention logits, edge-centric (no padding) ----------------
// warp takes 8 consecutive CSR edges (heads may differ): x = rel*agg[tail],
// y = x @ k_w (LDS.128 rank-1, kv amortized over a FULL 8 edges),
// att = dot(Q[head], tanh(y)) -> g_att.
__global__ void __launch_bounds__(256, 2) attA_kernel(const float* agg_in,
                                                      const float* __restrict__ edge_emb,
                                                      const float* __restrict__ kw) {
    // ksm layout: pair p, lane l: [p*64+2l], [p*64+2l+1] = K rows 2p,2p+1 at dims 2l,2l+1
    __shared__ ull ksm[EMB * 32];           // 16KB
    __shared__ ull relsm[NREL * 32];        // 8KB
    __shared__ ull xs[WARPS * EPA][EMB];    // 32KB
    const float* A = agg_in ? agg_in : g_agg;
    const ull* kw64 = (const ull*)kw;
    const ull* re64 = (const ull*)edge_emb;
    for (int idx = threadIdx.x; idx < EMB * 32; idx += blockDim.x) {
        int i = idx >> 5, lc = idx & 31;
        ksm[(i >> 1) * 64 + lc * 2 + (i & 1)] = kw64[idx];
    }
    for (int idx = threadIdx.x; idx < NREL * 32; idx += blockDim.x) relsm[idx] = re64[idx];
    __syncthreads();

    int w = threadIdx.x >> 5, l = threadIdx.x & 31;
    const float2* A2 = (const float2*)A;
    const float2* Q2 = (const float2*)g_Q;

    for (int base = (blockIdx.x * WARPS + w) * EPA; base < NEDGE;
         base += gridDim.x * WARPS * EPA) {
        int nv = NEDGE - base; if (nv > EPA) nv = EPA;
        float2 q[EPA];
        #pragma unroll
        for (int e = 0; e < EPA; e++) {
            float xa = 0.f, xb = 0.f;
            q[e] = make_float2(0.f, 0.f);
            if (e < nv) {
                int pw = g_packc[base + e];
                int h  = g_headc[base + e];
                int t = pw & 0x1FFFF, r = pw >> 17;
                float2 ag = A2[t * 32 + l];
                float2 rr = up2(relsm[r * 32 + l]);
                q[e] = Q2[h * 32 + l];
                xa = rr.x * ag.x; xb = rr.y * ag.y;
            }
            ((float4*)xs[w * EPA + e])[l] = make_float4(xa, xa, xb, xb);
        }
        __syncwarp();

        ull acc[EPA];
        #pragma unroll
        for (int e = 0; e < EPA; e++) acc[e] = 0ull;
        #pragma unroll 4
        for (int p = 0; p < 32; p++) {       // 2 K-rows per iter, kv amortized over 8 edges
            ulonglong2 kv = *(const ulonglong2*)&ksm[p * 64 + l * 2];
            #pragma unroll
            for (int e = 0; e < EPA; e++) {
                ulonglong2 xv = *(const ulonglong2*)&xs[w * EPA + e][2 * p];
                acc[e] = fma2(kv.x, xv.x, acc[e]);
                acc[e] = fma2(kv.y, xv.y, acc[e]);
            }
        }

        #pragma unroll
        for (int e = 0; e < EPA; e++) {
            float2 y = up2(acc[e]);
            float d = tanha(y.x) * q[e].x + tanha(y.y) * q[e].y;
            #pragma unroll
            for (int o = 16; o; o >>= 1) d += __shfl_xor_sync(0xffffffffu, d, o);
            if (l == e && e < nv) g_att[base + e] = d;
        }
        __syncwarp();
    }
}

// ---------------- pass B: softmax + weighted scatter-mean + l2norm + kg ----------------
// warp per head, no GEMM: sweep 1 finds the exact max; sweep 2 does
// exp + gather + accumulate with EPB prefetch. Light -> padding irrelevant.
__global__ void passB_kernel(const float* agg_in,
                             const float* __restrict__ edge_emb,
                             const float* __restrict__ ent,
                             float* kg, int accumulate, int write_agg) {
    __shared__ ull relsm[NREL * 32];
    const float* A = agg_in ? agg_in : g_agg;
    const ull* re64 = (const ull*)edge_emb;
    for (int idx = threadIdx.x; idx < NREL * 32; idx += blockDim.x) relsm[idx] = re64[idx];
    __syncthreads();

    int w = threadIdx.x >> 5, l = threadIdx.x & 31;
    const float2* A2 = (const float2*)A;
    const float2* E2 = (const float2*)ent;
    float2* KG2 = (float2*)kg;

    for (int h = blockIdx.x * WARPS + w; h < N_ENT; h += gridDim.x * WARPS) {
        int rs = g_rowptr[h], re = g_rowptr[h + 1];
        int deg = re - rs;

        // sweep 1: exact max of logits (uniform broadcast loads, L1/L2 resident)
        float m = neg_inf();
        int j = rs;
        for (; j + 4 <= re; j += 4) {
            float v0 = g_att[j], v1 = g_att[j + 1], v2 = g_att[j + 2], v3 = g_att[j + 3];
            m = fmaxf(m, fmaxf(fmaxf(v0, v1), fmaxf(v2, v3)));
        }
        for (; j < re; j++) m = fmaxf(m, g_att[j]);

        // sweep 2: exp + gather + accumulate
        float ssum = 0.f, a0 = 0.f, a1 = 0.f;
        int pwv[EPB]; float avv[EPB]; float2 nag[EPB];
        int j0 = rs;
        if (j0 < re) {
            int nv = re - j0; if (nv > EPB) nv = EPB;
            #pragma unroll
            for (int e = 0; e < EPB; e++) {
                pwv[e] = (e < nv) ? g_packc[j0 + e] : 0;
                avv[e] = (e < nv) ? g_att[j0 + e] : neg_inf();
                nag[e] = (e < nv) ? A2[(pwv[e] & 0x1FFFF) * 32 + l] : make_float2(0.f, 0.f);
            }
        }
        while (j0 < re) {
            float x0[EPB], x1[EPB], p[EPB];
            #pragma unroll
            for (int e = 0; e < EPB; e++) {
                float2 rr = up2(relsm[(pwv[e] >> 17) * 32 + l]);
                x0[e] = rr.x * nag[e].x;
                x1[e] = rr.y * nag[e].y;
                p[e]  = __expf(avv[e] - m);          // -inf slots -> 0
            }
            int j1 = j0 + EPB;
            if (j1 < re) {                           // prefetch next batch
                int nv2 = re - j1; if (nv2 > EPB) nv2 = EPB;
                #pragma unroll
                for (int e = 0; e < EPB; e++) {
                    pwv[e] = (e < nv2) ? g_packc[j1 + e] : 0;
                    avv[e] = (e < nv2) ? g_att[j1 + e] : neg_inf();
                    nag[e] = (e < nv2) ? A2[(pwv[e] & 0x1FFFF) * 32 + l] : make_float2(0.f, 0.f);
                }
            }
            #pragma unroll
            for (int e = 0; e < EPB; e++) {
                ssum += p[e];
                a0   += p[e] * x0[e];
                a1   += p[e] * x1[e];
            }
            j0 = j1;
        }

        float v0 = 0.f, v1 = 0.f;
        if (deg > 0) {
            float inv = 1.f / (ssum * (float)deg);   // softmax denom * scatter_mean count
            v0 = a0 * inv; v1 = a1 * inv;
        }
        float sq = v0 * v0 + v1 * v1;
        #pragma unroll
        for (int o = 16; o; o >>= 1) sq += __shfl_xor_sync(0xffffffffu, sq, o);
        float rn = 1.f / fmaxf(sqrtf(sq), 1e-12f);
        v0 *= rn; v1 *= rn;

        if (write_agg) ((float2*)g_agg)[h * 32 + l] = make_float2(v0, v1);
        float2 e2 = E2[h * 32 + l];
        float2 o2;
        if (accumulate) {
            float2 kold = KG2[h * 32 + l];
            o2 = make_float2(kold.x + v0 + e2.x, kold.y + v1 + e2.y);
        } else {
            o2 = make_float2(v0 + e2.x, v1 + e2.y);
        }
        KG2[h * 32 + l] = o2;
    }
}

// ---------------- launch ----------------
extern "C" void kernel_launch(void* const* d_in, const int* in_sizes, int n_in,
                              void* d_out, int out_size) {
    const float* ent      = (const float*)d_in[0];
    const float* edge_emb = (const float*)d_in[1];
    const float* qw       = (const float*)d_in[2];
    const float* kw       = (const float*)d_in[3];
    const int*   eidx     = (const int*)d_in[4];
    const int*   etype    = (const int*)d_in[5];
    const int* head = eidx;
    const int* tail = eidx + NEDGE;
    float* kg = (float*)d_out;

    // CSR build (head identical across hops -> build once per launch)
    zero_deg_kernel<<<(N_ENT + 255) / 256, 256>>>();
    count_kernel<<<(NEDGE + 255) / 256, 256>>>(head);
    scan1_kernel<<<SCAN_BLKS, 1024>>>();
    scan2_kernel<<<1, 128>>>();
    scan3_kernel<<<(N_ENT + 255) / 256, 256>>>();
    fill_kernel<<<(NEDGE + 255) / 256, 256>>>(head, tail, etype);

    // hop 1: agg = entity_emb
    gemmq_kernel<<<2048, 256>>>(ent, qw);
    attA_kernel<<<3125, 256>>>(ent, edge_emb, kw);
    passB_kernel<<<3125, 256>>>(ent, edge_emb, ent, kg, /*accumulate=*/0, /*write_agg=*/1);

    // hop 2: agg = g_agg
    gemmq_kernel<<<2048, 256>>>(nullptr, qw);
    attA_kernel<<<3125, 256>>>(nullptr, edge_emb, kw);
    passB_kernel<<<3125, 256>>>(nullptr, edge_emb, ent, kg, /*accumulate=*/1, /*write_agg=*/0);
}

// round 11
// speedup vs baseline: 1.5715x; 1.2909x over previous
#include <cuda_runtime.h>

#define N_ENT  100000
#define EMB    64
#define NREL   32
#define NEDGE  1000000
#define WARPS  8
#define EPA    8    // edges per warp-batch in attA (NEDGE % EPA == 0 -> always full)
#define EPB    4    // edges per batch in passB
#define SCAN_BLKS ((N_ENT + 1023) / 1024)   // 98

typedef unsigned long long ull;

// ---------------- static device scratch (no allocation allowed) ----------------
__device__ float g_Q[N_ENT * EMB];       // (agg @ q_w)
__device__ float g_agg[N_ENT * EMB];     // agg after hop 1
__device__ float g_att[NEDGE];           // attention logits (CSR order)
__device__ int   g_deg[N_ENT];
__device__ int   g_rowptr[N_ENT + 1];
__device__ int   g_cursor[N_ENT];
__device__ int   g_bsum[128];            // scan block sums
__device__ int   g_packc[NEDGE];         // CSR-ordered (tail | type<<17)
__device__ int   g_headc[NEDGE];         // CSR-ordered head

// ---------------- PTX helpers (sm_100+) ----------------
__device__ __forceinline__ ull fma2(ull a, ull b, ull c) {
    ull d;
    asm("fma.rn.f32x2 %0, %1, %2, %3;" : "=l"(d) : "l"(a), "l"(b), "l"(c));
    return d;
}
__device__ __forceinline__ float2 up2(ull v) {
    float2 f;
    asm("mov.b64 {%0, %1}, %2;" : "=f"(f.x), "=f"(f.y) : "l"(v));
    return f;
}
__device__ __forceinline__ float tanha(float x) {
    float y;
    asm("tanh.approx.f32 %0, %1;" : "=f"(y) : "f"(x));
    return y;
}
__device__ __forceinline__ float neg_inf() { return __int_as_float(0xff800000U); }

// ---------------- CSR build ----------------
__global__ void zero_deg_kernel() {
    int i = blockIdx.x * blockDim.x + threadIdx.x;
    if (i < N_ENT) g_deg[i] = 0;
}

__global__ void count_kernel(const int* __restrict__ head) {
    int e = blockIdx.x * blockDim.x + threadIdx.x;
    if (e < NEDGE) atomicAdd(&g_deg[head[e]], 1);
}

__global__ void scan1_kernel() {
    __shared__ int sh[1024];
    int tid = threadIdx.x;
    int i = blockIdx.x * 1024 + tid;
    int v = (i < N_ENT) ? g_deg[i] : 0;
    sh[tid] = v;
    __syncthreads();
    for (int off = 1; off < 1024; off <<= 1) {
        int t = (tid >= off) ? sh[tid - off] : 0;
        __syncthreads();
        sh[tid] += t;
        __syncthreads();
    }
    if (i < N_ENT) g_rowptr[i] = sh[tid] - v;
    if (tid == 1023) g_bsum[blockIdx.x] = sh[1023];
}

__global__ void scan2_kernel() {
    __shared__ int sh[128];
    int tid = threadIdx.x;
    int v = (tid < SCAN_BLKS) ? g_bsum[tid] : 0;
    sh[tid] = v;
    __syncthreads();
    for (int off = 1; off < 128; off <<= 1) {
        int t = (tid >= off) ? sh[tid - off] : 0;
        __syncthreads();
        sh[tid] += t;
        __syncthreads();
    }
    g_bsum[tid] = sh[tid] - v;
}

__global__ void scan3_kernel() {
    int i = blockIdx.x * blockDim.x + threadIdx.x;
    if (i < N_ENT) {
        int r = g_rowptr[i] + g_bsum[i >> 10];
        g_rowptr[i] = r;
        g_cursor[i] = r;
    }
    if (i == 0) g_rowptr[N_ENT] = NEDGE;
}

__global__ void fill_kernel(const int* __restrict__ head,
                            const int* __restrict__ tail,
                            const int* __restrict__ etype) {
    int e = blockIdx.x * blockDim.x + threadIdx.x;
    if (e < NEDGE) {
        int h = head[e];
        int pos = atomicAdd(&g_cursor[h], 1);
        g_packc[pos] = tail[e] | (etype[e] << 17);   // N_ENT < 2^17, NREL < 2^5
        g_headc[pos] = h;
    }
}

// ---------------- Q = agg @ q_w   (warp per row, packed f32x2 FMA) ----------------
__global__ void gemmq_kernel(const float* agg_in, const float* __restrict__ qw) {
    __shared__ ull qsm[EMB * 32];
    __shared__ ull xs[WARPS][EMB];
    const float* A = agg_in ? agg_in : g_agg;
    const ull* qw64 = (const ull*)qw;
    for (int idx = threadIdx.x; idx < EMB * 32; idx += blockDim.x) qsm[idx] = qw64[idx];
    __syncthreads();
    int w = threadIdx.x >> 5, l = threadIdx.x & 31;
    const float2* A2 = (const float2*)A;
    for (int row = blockIdx.x * WARPS + w; row < N_ENT; row += gridDim.x * WARPS) {
        float2 a2 = A2[row * 32 + l];
        ((float4*)xs[w])[l] = make_float4(a2.x, a2.x, a2.y, a2.y);
        __syncwarp();
        ull acc = 0ull;
        #pragma unroll 8
        for (int i = 0; i < EMB; i++) acc = fma2(qsm[i * 32 + l], xs[w][i], acc);
        float2 r = up2(acc);
        ((float2*)g_Q)[row * 32 + l] = r;
        __syncwarp();
    }
}

// ---------------- pass A: attention logits, edge-centric (no padding) ----------------
// f32x2 lanes carry (even-k, odd-k) partial sums: x stored UNDUPLICATED, so each
// broadcast LDS.128 feeds 4 fma2. K pre-packed lane-major (ksmA: out-dim 2l,
// ksmB: out-dim 2l+1) so kv reads are conflict-free LDS.128 amortized over 8 edges.
__global__ void __launch_bounds__(256, 2) attA_kernel(const float* agg_in,
                                                      const float* __restrict__ edge_emb,
                                                      const float* __restrict__ kw) {
    __shared__ float4 ksmA[16 * 32];        // 8KB : [kb][l] = kw[4kb..4kb+3][2l]
    __shared__ float4 ksmB[16 * 32];        // 8KB : [kb][l] = kw[4kb..4kb+3][2l+1]
    __shared__ ull relsm[NREL * 32];        // 8KB
    __shared__ __align__(16) float xs[WARPS][EPA][EMB];  // 16KB (undup'd)
    const float* A = agg_in ? agg_in : g_agg;
    const ull* re64 = (const ull*)edge_emb;

    for (int idx = threadIdx.x; idx < 16 * 32; idx += blockDim.x) {
        int kb = idx >> 5, lc = idx & 31;
        int k0 = kb * 4;
        int d0 = lc * 2, d1 = lc * 2 + 1;
        ksmA[idx] = make_float4(kw[(k0 + 0) * EMB + d0], kw[(k0 + 1) * EMB + d0],
                                kw[(k0 + 2) * EMB + d0], kw[(k0 + 3) * EMB + d0]);
        ksmB[idx] = make_float4(kw[(k0 + 0) * EMB + d1], kw[(k0 + 1) * EMB + d1],
                                kw[(k0 + 2) * EMB + d1], kw[(k0 + 3) * EMB + d1]);
    }
    for (int idx = threadIdx.x; idx < NREL * 32; idx += blockDim.x) relsm[idx] = re64[idx];
    __syncthreads();

    int w = threadIdx.x >> 5, l = threadIdx.x & 31;
    const float2* A2 = (const float2*)A;
    const float2* Q2 = (const float2*)g_Q;

    for (int base = (blockIdx.x * WARPS + w) * EPA; base < NEDGE;
         base += gridDim.x * WARPS * EPA) {
        // NEDGE % EPA == 0 -> batch always full
        float2 q[EPA];
        #pragma unroll
        for (int e = 0; e < EPA; e++) {
            int pw = g_packc[base + e];
            int h  = g_headc[base + e];
            int t = pw & 0x1FFFF, r = pw >> 17;
            float2 ag = A2[t * 32 + l];
            float2 rr = up2(relsm[r * 32 + l]);
            q[e] = Q2[h * 32 + l];
            ((float2*)xs[w][e])[l] = make_float2(rr.x * ag.x, rr.y * ag.y);
        }
        __syncwarp();

        ull acc0[EPA], acc1[EPA];
        #pragma unroll
        for (int e = 0; e < EPA; e++) { acc0[e] = 0ull; acc1[e] = 0ull; }
        #pragma unroll
        for (int kb = 0; kb < 16; kb++) {
            ulonglong2 ka = *(const ulonglong2*)&ksmA[kb * 32 + l];  // reused by 8 edges
            ulonglong2 kbv = *(const ulonglong2*)&ksmB[kb * 32 + l];
            #pragma unroll
            for (int e = 0; e < EPA; e++) {
                ulonglong2 xv = *(const ulonglong2*)&xs[w][e][kb * 4];  // broadcast, 4 k's
                acc0[e] = fma2(xv.x, ka.x, acc0[e]);
                acc0[e] = fma2(xv.y, ka.y, acc0[e]);
                acc1[e] = fma2(xv.x, kbv.x, acc1[e]);
                acc1[e] = fma2(xv.y, kbv.y, acc1[e]);
            }
        }

        #pragma unroll
        for (int e = 0; e < EPA; e++) {
            float2 s0 = up2(acc0[e]);   // (even-k sum, odd-k sum) for dim 2l
            float2 s1 = up2(acc1[e]);   // same for dim 2l+1
            float d = tanha(s0.x + s0.y) * q[e].x + tanha(s1.x + s1.y) * q[e].y;
            #pragma unroll
            for (int o = 16; o; o >>= 1) d += __shfl_xor_sync(0xffffffffu, d, o);
            if (l == e) g_att[base + e] = d;
        }
        __syncwarp();
    }
}

// ---------------- pass B: softmax + weighted scatter-mean + l2norm + kg ----------------
__global__ void passB_kernel(const float* agg_in,
                             const float* __restrict__ edge_emb,
                             const float* __restrict__ ent,
                             float* kg, int accumulate, int write_agg) {
    __shared__ ull relsm[NREL * 32];
    const float* A = agg_in ? agg_in : g_agg;
    const ull* re64 = (const ull*)edge_emb;
    for (int idx = threadIdx.x; idx < NREL * 32; idx += blockDim.x) relsm[idx] = re64[idx];
    __syncthreads();

    int w = threadIdx.x >> 5, l = threadIdx.x & 31;
    const float2* A2 = (const float2*)A;
    const float2* E2 = (const float2*)ent;
    float2* KG2 = (float2*)kg;

    for (int h = blockIdx.x * WARPS + w; h < N_ENT; h += gridDim.x * WARPS) {
        int rs = g_rowptr[h], re = g_rowptr[h + 1];
        int deg = re - rs;

        // sweep 1: exact max of logits (uniform broadcast loads, L1/L2 resident)
        float m = neg_inf();
        int j = rs;
        for (; j + 4 <= re; j += 4) {
            float v0 = g_att[j], v1 = g_att[j + 1], v2 = g_att[j + 2], v3 = g_att[j + 3];
            m = fmaxf(m, fmaxf(fmaxf(v0, v1), fmaxf(v2, v3)));
        }
        for (; j < re; j++) m = fmaxf(m, g_att[j]);

        // sweep 2: exp + gather + accumulate
        float ssum = 0.f, a0 = 0.f, a1 = 0.f;
        int pwv[EPB]; float avv[EPB]; float2 nag[EPB];
        int j0 = rs;
        if (j0 < re) {
            int nv = re - j0; if (nv > EPB) nv = EPB;
            #pragma unroll
            for (int e = 0; e < EPB; e++) {
                pwv[e] = (e < nv) ? g_packc[j0 + e] : 0;
                avv[e] = (e < nv) ? g_att[j0 + e] : neg_inf();
                nag[e] = (e < nv) ? A2[(pwv[e] & 0x1FFFF) * 32 + l] : make_float2(0.f, 0.f);
            }
        }
        while (j0 < re) {
            float x0[EPB], x1[EPB], p[EPB];
            #pragma unroll
            for (int e = 0; e < EPB; e++) {
                float2 rr = up2(relsm[(pwv[e] >> 17) * 32 + l]);
                x0[e] = rr.x * nag[e].x;
                x1[e] = rr.y * nag[e].y;
                p[e]  = __expf(avv[e] - m);          // -inf slots -> 0
            }
            int j1 = j0 + EPB;
            if (j1 < re) {                           // prefetch next batch
                int nv2 = re - j1; if (nv2 > EPB) nv2 = EPB;
                #pragma unroll
                for (int e = 0; e < EPB; e++) {
                    pwv[e] = (e < nv2) ? g_packc[j1 + e] : 0;
                    avv[e] = (e < nv2) ? g_att[j1 + e] : neg_inf();
                    nag[e] = (e < nv2) ? A2[(pwv[e] & 0x1FFFF) * 32 + l] : make_float2(0.f, 0.f);
                }
            }
            #pragma unroll
            for (int e = 0; e < EPB; e++) {
                ssum += p[e];
                a0   += p[e] * x0[e];
                a1   += p[e] * x1[e];
            }
            j0 = j1;
        }

        float v0 = 0.f, v1 = 0.f;
        if (deg > 0) {
            float inv = 1.f / (ssum * (float)deg);   // softmax denom * scatter_mean count
            v0 = a0 * inv; v1 = a1 * inv;
        }
        float sq = v0 * v0 + v1 * v1;
        #pragma unroll
        for (int o = 16; o; o >>= 1) sq += __shfl_xor_sync(0xffffffffu, sq, o);
        float rn = 1.f / fmaxf(sqrtf(sq), 1e-12f);
        v0 *= rn; v1 *= rn;

        if (write_agg) ((float2*)g_agg)[h * 32 + l] = make_float2(v0, v1);
        float2 e2 = E2[h * 32 + l];
        float2 o2;
        if (accumulate) {
            float2 kold = KG2[h * 32 + l];
            o2 = make_float2(kold.x + v0 + e2.x, kold.y + v1 + e2.y);
        } else {
            o2 = make_float2(v0 + e2.x, v1 + e2.y);
        }
        KG2[h * 32 + l] = o2;
    }
}

// ---------------- launch ----------------
extern "C" void kernel_launch(void* const* d_in, const int* in_sizes, int n_in,
                              void* d_out, int out_size) {
    const float* ent      = (const float*)d_in[0];
    const float* edge_emb = (const float*)d_in[1];
    const float* qw       = (const float*)d_in[2];
    const float* kw       = (const float*)d_in[3];
    const int*   eidx     = (const int*)d_in[4];
    const int*   etype    = (const int*)d_in[5];
    const int* head = eidx;
    const int* tail = eidx + NEDGE;
    float* kg = (float*)d_out;

    // CSR build (head identical across hops -> build once per launch)
    zero_deg_kernel<<<(N_ENT + 255) / 256, 256>>>();
    count_kernel<<<(NEDGE + 255) / 256, 256>>>(head);
    scan1_kernel<<<SCAN_BLKS, 1024>>>();
    scan2_kernel<<<1, 128>>>();
    scan3_kernel<<<(N_ENT + 255) / 256, 256>>>();
    fill_kernel<<<(NEDGE + 255) / 256, 256>>>(head, tail, etype);

    // hop 1: agg = entity_emb
    gemmq_kernel<<<2048, 256>>>(ent, qw);
    attA_kernel<<<3125, 256>>>(ent, edge_emb, kw);
    passB_kernel<<<3125, 256>>>(ent, edge_emb, ent, kg, /*accumulate=*/0, /*write_agg=*/1);

    // hop 2: agg = g_agg
    gemmq_kernel<<<2048, 256>>>(nullptr, qw);
    attA_kernel<<<3125, 256>>>(nullptr, edge_emb, kw);
    passB_kernel<<<3125, 256>>>(nullptr, edge_emb, ent, kg, /*accumulate=*/1, /*write_agg=*/0);
}